// round 15
// baseline (speedup 1.0000x reference)
#include <cuda_runtime.h>
#include <cuda_fp16.h>

// DagEncoder via warp-level fp16 mma.sync (single-term fp16 weights).
// R15: hoist W2 B-fragments into registers (tile-invariant; kills 16 ldsm +
// 8KB smem traffic per tile), launch_bounds(128,3), L2 prefetch of next tile.

#define MAX_DAGS  20000
#define MAX_NODES 2000000
__device__ float g_acc[MAX_DAGS * 64];
__device__ int   g_ptr[MAX_DAGS + 1];
__device__ int   g_seg[MAX_NODES];

typedef unsigned int u32;

__device__ __forceinline__ u32 smem_u32(const void* p) {
    u32 a;
    asm("{ .reg .u64 t; cvta.to.shared.u64 t, %1; cvt.u32.u64 %0, t; }"
        : "=r"(a) : "l"(p));
    return a;
}
__device__ __forceinline__ u32 f16pair(float v0, float v1) {
    u32 d;
    asm("cvt.rn.f16x2.f32 %0, %1, %2;" : "=r"(d) : "f"(v1), "f"(v0));
    return d;
}
__device__ __forceinline__ void ldsm_x4(u32 a, u32* r) {
    asm volatile("ldmatrix.sync.aligned.m8n8.x4.shared.b16 {%0,%1,%2,%3}, [%4];"
        : "=r"(r[0]), "=r"(r[1]), "=r"(r[2]), "=r"(r[3]) : "r"(a));
}
__device__ __forceinline__ void ldsm_x4t(u32 a, u32* r) {
    asm volatile("ldmatrix.sync.aligned.m8n8.x4.trans.shared.b16 {%0,%1,%2,%3}, [%4];"
        : "=r"(r[0]), "=r"(r[1]), "=r"(r[2]), "=r"(r[3]) : "r"(a));
}
__device__ __forceinline__ void mma_f16(float* d, const u32* a, u32 b0, u32 b1) {
    asm("mma.sync.aligned.m16n8k16.row.col.f32.f16.f16.f32 "
        "{%0,%1,%2,%3},{%4,%5,%6,%7},{%8,%9},{%0,%1,%2,%3};"
        : "+f"(d[0]), "+f"(d[1]), "+f"(d[2]), "+f"(d[3])
        : "r"(a[0]), "r"(a[1]), "r"(a[2]), "r"(a[3]), "r"(b0), "r"(b1));
}
__device__ __forceinline__ void pf_l2(const void* p) {
    asm volatile("prefetch.global.L2 [%0];" :: "l"(p));
}

__global__ void prep_kernel(const void* __restrict__ ptr_raw,
                            int num_dags, int num_nodes) {
    const int*       p32 = (const int*)ptr_raw;
    const long long* p64 = (const long long*)ptr_raw;
    const bool is32 = (p32[num_dags] == num_nodes);
    const int w = (blockIdx.x * blockDim.x + threadIdx.x) >> 5;
    const int lane = threadIdx.x & 31;
    if (w > num_dags) return;
    if (w == num_dags) { if (lane == 0) g_ptr[num_dags] = num_nodes; return; }
    const int b0 = is32 ? p32[w] : (int)p64[w];
    const int b1 = is32 ? p32[w + 1] : (int)p64[w + 1];
    if (lane == 0) g_ptr[w] = b0;
    if (lane < 16)
        ((float4*)&g_acc[(size_t)w * 64])[lane] = make_float4(0.f, 0.f, 0.f, 0.f);
    for (int i = b0 + lane; i < b1; i += 32) g_seg[i] = w;
}

// smem: W1[48][72]f16 @0 (6912), W2[64][72] @6912 (9216),
//       b1 @16128, b2 @16384; per-warp act scratch 3584B @16640 + w*3584
#define OFF_W1  0
#define OFF_W2  6912
#define OFF_B1  16128
#define OFF_B2  16384
#define OFF_SCR 16640
#define SCR_WARP 3584
#define SMEM_SZ (OFF_SCR + 4 * SCR_WARP)

__global__ __launch_bounds__(128, 3) void mma_seg_kernel(
    const float* __restrict__ h_node, const float* __restrict__ x,
    const float* __restrict__ W1, const float* __restrict__ b1,
    const float* __restrict__ W2, const float* __restrict__ b2,
    int num_nodes, int ntiles)
{
    extern __shared__ __align__(16) unsigned char sm[];
    const int tid = threadIdx.x, lane = tid & 31, w = tid >> 5;

    for (int i = tid; i < 48 * 72; i += 128) {
        int k = i / 72, n = i % 72;
        float v = (k < 37 && n < 64) ? W1[k * 64 + n] : 0.0f;
        *(__half*)(sm + OFF_W1 + i * 2) = __float2half_rn(v);
    }
    for (int i = tid; i < 64 * 72; i += 128) {
        int k = i / 72, n = i % 72;
        float v = (n < 64) ? W2[k * 64 + n] : 0.0f;
        *(__half*)(sm + OFF_W2 + i * 2) = __float2half_rn(v);
    }
    if (tid < 64) {
        ((float*)(sm + OFF_B1))[tid] = b1[tid];
        ((float*)(sm + OFF_B2))[tid] = b2[tid];
    }
    __syncthreads();

    unsigned char* scrp = sm + OFF_SCR + w * SCR_WARP;
    const u32 scr = smem_u32(scrp);
    const u32 w1s = smem_u32(sm + OFF_W1);
    const u32 w2s = smem_u32(sm + OFF_W2);
    const float* B1s = (const float*)(sm + OFF_B1);
    const float* B2s = (const float*)(sm + OFF_B2);

    const int g = lane >> 2, t = lane & 3;
    const int lrow = lane & 15, lcs = lane >> 4;
    const unsigned FULL = 0xffffffffu;
    const int wid_g = blockIdx.x * 4 + w, nW = gridDim.x * 4;

    // ---- hoist W2 B-fragments (tile-invariant): 16 ldsm.x4 -> 64 regs ----
    u32 w2f[4][4][4];
#pragma unroll
    for (int npg = 0; npg < 4; npg++)
#pragma unroll
        for (int kt = 0; kt < 4; kt++)
            ldsm_x4t(w2s + (kt * 16 + lrow) * 144 + (npg * 16 + lcs * 8) * 2,
                     w2f[npg][kt]);

    for (int tile = wid_g; tile < ntiles; tile += nW) {
        const int node0 = tile * 32;
        const int node = node0 + lane;
        const bool valid = node < num_nodes;

        // L2 prefetch next tile's inputs (no registers held)
        {
            const int nn = node + nW * 32;
            if (nn < num_nodes) {
                pf_l2(x + (size_t)nn * 5);
                pf_l2(h_node + (size_t)nn * 32);
                pf_l2(g_seg + nn);
            }
        }

        // ---- load + convert to packed fp16 on the fly ----
        u32 ah[24];
#pragma unroll
        for (int j = 0; j < 24; j++) ah[j] = 0u;
        int seg = -1;
        if (valid) {
            const float* xp = x + (size_t)node * 5;
            float x0 = xp[0], x1 = xp[1], x2 = xp[2], x3 = xp[3], x4 = xp[4];
            const float4* hp = (const float4*)(h_node + (size_t)node * 32);
            ah[0] = f16pair(x0, x1);
            ah[1] = f16pair(x2, x3);
            float carry = x4;
#pragma unroll
            for (int i = 0; i < 8; i++) {
                float4 v4 = hp[i];
                ah[2 + 2 * i] = f16pair(carry, v4.x);
                ah[3 + 2 * i] = f16pair(v4.y, v4.z);
                carry = v4.w;
            }
            ah[18] = f16pair(carry, 0.0f);
            seg = g_seg[node];
        }

        // segment classification
        int segup = __shfl_up_sync(FULL, seg, 1);
        bool head = valid && (lane == 0 || segup != seg);
        unsigned bm = __ballot_sync(FULL, head);
        const int nsegs = __popc(bm);
        int segA = 0, segB = 0, rowb = 32;
        if (nsegs > 0) segA = __shfl_sync(FULL, seg, __ffs(bm) - 1);
        if (nsegs >= 2) {
            unsigned bm2 = bm & (bm - 1);
            rowb = __ffs(bm2) - 1;
            segB = __shfl_sync(FULL, seg, rowb);
        }
        const bool fast = (nsegs <= 2);

        __syncwarp();  // scratch reuse vs previous iteration
        {
            uint4* dh = (uint4*)(scrp + lane * 112);
#pragma unroll
            for (int j = 0; j < 6; j++)
                dh[j] = make_uint4(ah[4*j], ah[4*j+1], ah[4*j+2], ah[4*j+3]);
        }
        __syncwarp();

        // layer-1 A fragments (M32 K48)
        u32 a1[2][3][4];
#pragma unroll
        for (int mt = 0; mt < 2; mt++)
#pragma unroll
            for (int kt = 0; kt < 3; kt++)
                ldsm_x4(scr + (mt * 16 + lrow) * 112 + (kt * 16 + lcs * 8) * 2,
                        a1[mt][kt]);

        // ---- layer 1 MMA -> layer-2 A frags in registers ----
        u32 a2[2][4][4];
#pragma unroll
        for (int half = 0; half < 2; half++) {
            float d[2][4][4];
#pragma unroll
            for (int ntl = 0; ntl < 4; ntl++) {
                float2 bb = *(const float2*)(B1s + (half * 4 + ntl) * 8 + 2 * t);
#pragma unroll
                for (int mt = 0; mt < 2; mt++) {
                    d[mt][ntl][0] = bb.x; d[mt][ntl][1] = bb.y;
                    d[mt][ntl][2] = bb.x; d[mt][ntl][3] = bb.y;
                }
            }
#pragma unroll
            for (int np = 0; np < 2; np++) {
                int npg = half * 2 + np;
                u32 bh[3][4];
#pragma unroll
                for (int kt = 0; kt < 3; kt++)
                    ldsm_x4t(w1s + (kt * 16 + lrow) * 144 + (npg * 16 + lcs * 8) * 2,
                             bh[kt]);
#pragma unroll
                for (int mt = 0; mt < 2; mt++)
#pragma unroll
                    for (int kt = 0; kt < 3; kt++)
#pragma unroll
                        for (int hh = 0; hh < 2; hh++)
                            mma_f16(d[mt][np * 2 + hh], a1[mt][kt],
                                    bh[kt][2*hh], bh[kt][2*hh+1]);
            }
#pragma unroll
            for (int mt = 0; mt < 2; mt++)
#pragma unroll
                for (int ntl = 0; ntl < 4; ntl++) {
                    int ng = half * 4 + ntl;
                    int ktg = ng >> 1, sub = ng & 1;
                    a2[mt][ktg][sub * 2 + 0] =
                        f16pair(fmaxf(d[mt][ntl][0], 0.f), fmaxf(d[mt][ntl][1], 0.f));
                    a2[mt][ktg][sub * 2 + 1] =
                        f16pair(fmaxf(d[mt][ntl][2], 0.f), fmaxf(d[mt][ntl][3], 0.f));
                }
        }

        // ---- layer 2 MMA (B from hoisted registers); epilogue reduce ----
#pragma unroll
        for (int half = 0; half < 2; half++) {
            float d[2][4][4];
#pragma unroll
            for (int ntl = 0; ntl < 4; ntl++) {
                float2 bb = *(const float2*)(B2s + (half * 4 + ntl) * 8 + 2 * t);
#pragma unroll
                for (int mt = 0; mt < 2; mt++) {
                    d[mt][ntl][0] = bb.x; d[mt][ntl][1] = bb.y;
                    d[mt][ntl][2] = bb.x; d[mt][ntl][3] = bb.y;
                }
            }
#pragma unroll
            for (int np = 0; np < 2; np++) {
                int npg = half * 2 + np;
#pragma unroll
                for (int mt = 0; mt < 2; mt++)
#pragma unroll
                    for (int kt = 0; kt < 4; kt++)
#pragma unroll
                        for (int hh = 0; hh < 2; hh++)
                            mma_f16(d[mt][np * 2 + hh], a2[mt][kt],
                                    w2f[npg][kt][2*hh], w2f[npg][kt][2*hh+1]);
            }

            // relu + validity
#pragma unroll
            for (int mt = 0; mt < 2; mt++)
#pragma unroll
                for (int ntl = 0; ntl < 4; ntl++) {
                    bool ok0 = (node0 + mt * 16 + g) < num_nodes;
                    bool ok1 = (node0 + mt * 16 + g + 8) < num_nodes;
                    d[mt][ntl][0] = ok0 ? fmaxf(d[mt][ntl][0], 0.f) : 0.f;
                    d[mt][ntl][1] = ok0 ? fmaxf(d[mt][ntl][1], 0.f) : 0.f;
                    d[mt][ntl][2] = ok1 ? fmaxf(d[mt][ntl][2], 0.f) : 0.f;
                    d[mt][ntl][3] = ok1 ? fmaxf(d[mt][ntl][3], 0.f) : 0.f;
                }

            if (fast) {
                if (nsegs > 0) {
#pragma unroll
                    for (int ntl = 0; ntl < 4; ntl++) {
                        float sA0 = 0.f, sA1 = 0.f, sB0 = 0.f, sB1v = 0.f;
#pragma unroll
                        for (int mt = 0; mt < 2; mt++) {
                            int r0 = mt * 16 + g, r1 = r0 + 8;
                            if (r0 < rowb) { sA0 += d[mt][ntl][0]; sA1 += d[mt][ntl][1]; }
                            else           { sB0 += d[mt][ntl][0]; sB1v += d[mt][ntl][1]; }
                            if (r1 < rowb) { sA0 += d[mt][ntl][2]; sA1 += d[mt][ntl][3]; }
                            else           { sB0 += d[mt][ntl][2]; sB1v += d[mt][ntl][3]; }
                        }
#pragma unroll
                        for (int m = 4; m <= 16; m <<= 1) {
                            sA0 += __shfl_xor_sync(FULL, sA0, m);
                            sA1 += __shfl_xor_sync(FULL, sA1, m);
                        }
                        if (nsegs == 2) {
#pragma unroll
                            for (int m = 4; m <= 16; m <<= 1) {
                                sB0 += __shfl_xor_sync(FULL, sB0, m);
                                sB1v += __shfl_xor_sync(FULL, sB1v, m);
                            }
                        }
                        if (g == 0) {
                            int c = half * 32 + ntl * 8 + 2 * t;
                            atomicAdd(&g_acc[(size_t)segA * 64 + c], sA0);
                            atomicAdd(&g_acc[(size_t)segA * 64 + c + 1], sA1);
                            if (nsegs == 2) {
                                atomicAdd(&g_acc[(size_t)segB * 64 + c], sB0);
                                atomicAdd(&g_acc[(size_t)segB * 64 + c + 1], sB1v);
                            }
                        }
                    }
                }
            } else {  // rare (>=3 segs): direct guarded atomics
#pragma unroll
                for (int mt = 0; mt < 2; mt++) {
                    int s0 = __shfl_sync(FULL, seg, mt * 16 + g);
                    int s1 = __shfl_sync(FULL, seg, mt * 16 + g + 8);
#pragma unroll
                    for (int ntl = 0; ntl < 4; ntl++) {
                        int c = (half * 4 + ntl) * 8 + 2 * t;
                        if (s0 >= 0) {
                            atomicAdd(&g_acc[(size_t)s0 * 64 + c], d[mt][ntl][0]);
                            atomicAdd(&g_acc[(size_t)s0 * 64 + c + 1], d[mt][ntl][1]);
                        }
                        if (s1 >= 0) {
                            atomicAdd(&g_acc[(size_t)s1 * 64 + c], d[mt][ntl][2]);
                            atomicAdd(&g_acc[(size_t)s1 * 64 + c + 1], d[mt][ntl][3]);
                        }
                    }
                }
            }
        }
    }
}

__global__ __launch_bounds__(256) void final_kernel(
    const float* __restrict__ W3, const float* __restrict__ b3,
    float* __restrict__ out, int num_dags)
{
    __shared__ __align__(16) float sW3[64 * 32];
    __shared__ float sB3[32];
    const int tid = threadIdx.x;
    for (int i = tid; i < 64 * 32; i += 256) sW3[i] = W3[i];
    if (tid < 32) sB3[tid] = b3[tid];
    __syncthreads();
    const int d = blockIdx.x * 8 + (tid >> 5);
    const int e = tid & 31;
    if (d >= num_dags) return;
    const float cnt = (float)(g_ptr[d + 1] - g_ptr[d]);
    float acc = cnt * sB3[e];
    const float* gd = &g_acc[(size_t)d * 64];
#pragma unroll
    for (int k = 0; k < 64; k++)
        acc = fmaf(gd[k], sW3[k * 32 + e], acc);
    out[(size_t)d * 32 + e] = acc;
}

extern "C" void kernel_launch(void* const* d_in, const int* in_sizes, int n_in,
                              void* d_out, int out_size)
{
    const float* h_node = (const float*)d_in[0];
    const float* x      = (const float*)d_in[1];
    const float* W1     = (const float*)d_in[2];
    const float* b1     = (const float*)d_in[3];
    const float* W2     = (const float*)d_in[4];
    const float* b2     = (const float*)d_in[5];
    const float* W3     = (const float*)d_in[6];
    const float* b3     = (const float*)d_in[7];
    const void*  ptr    = (const void*)d_in[8];

    const int num_nodes = in_sizes[0] / 32;
    const int num_dags  = in_sizes[8] - 1;
    const int ntiles    = (num_nodes + 31) / 32;

    static int grid_cached = 0;
    if (!grid_cached) {
        cudaFuncSetAttribute(mma_seg_kernel,
                             cudaFuncAttributeMaxDynamicSharedMemorySize, SMEM_SZ);
        int occ = 0, sms = 0;
        cudaOccupancyMaxActiveBlocksPerMultiprocessor(&occ, mma_seg_kernel,
                                                      128, SMEM_SZ);
        cudaDeviceGetAttribute(&sms, cudaDevAttrMultiProcessorCount, 0);
        if (occ < 1) occ = 1;
        if (sms < 1) sms = 148;
        grid_cached = occ * sms;
    }

    prep_kernel<<<((num_dags + 1) * 32 + 255) / 256, 256>>>(ptr, num_dags, num_nodes);

    int grid = grid_cached;
    if (grid > (ntiles + 3) / 4) grid = (ntiles + 3) / 4;
    mma_seg_kernel<<<grid, 128, SMEM_SZ>>>(h_node, x, W1, b1, W2, b2,
                                           num_nodes, ntiles);

    final_kernel<<<(num_dags + 7) / 8, 256>>>(W3, b3, (float*)d_out, num_dags);
}

// round 16
// speedup vs baseline: 1.0482x; 1.0482x over previous
#include <cuda_runtime.h>
#include <cuda_fp16.h>

// DagEncoder via warp-level fp16 mma.sync (single-term fp16 weights).
// R16 = R14 champion + branchless clamped loads + nsegs==1 fast path.

#define MAX_DAGS  20000
#define MAX_NODES 2000000
__device__ float g_acc[MAX_DAGS * 64];
__device__ int   g_ptr[MAX_DAGS + 1];
__device__ int   g_seg[MAX_NODES];

typedef unsigned int u32;

__device__ __forceinline__ u32 smem_u32(const void* p) {
    u32 a;
    asm("{ .reg .u64 t; cvta.to.shared.u64 t, %1; cvt.u32.u64 %0, t; }"
        : "=r"(a) : "l"(p));
    return a;
}
__device__ __forceinline__ u32 f16pair(float v0, float v1) {
    u32 d;
    asm("cvt.rn.f16x2.f32 %0, %1, %2;" : "=r"(d) : "f"(v1), "f"(v0));
    return d;
}
__device__ __forceinline__ void ldsm_x4(u32 a, u32* r) {
    asm volatile("ldmatrix.sync.aligned.m8n8.x4.shared.b16 {%0,%1,%2,%3}, [%4];"
        : "=r"(r[0]), "=r"(r[1]), "=r"(r[2]), "=r"(r[3]) : "r"(a));
}
__device__ __forceinline__ void ldsm_x4t(u32 a, u32* r) {
    asm volatile("ldmatrix.sync.aligned.m8n8.x4.trans.shared.b16 {%0,%1,%2,%3}, [%4];"
        : "=r"(r[0]), "=r"(r[1]), "=r"(r[2]), "=r"(r[3]) : "r"(a));
}
__device__ __forceinline__ void mma_f16(float* d, const u32* a, u32 b0, u32 b1) {
    asm("mma.sync.aligned.m16n8k16.row.col.f32.f16.f16.f32 "
        "{%0,%1,%2,%3},{%4,%5,%6,%7},{%8,%9},{%0,%1,%2,%3};"
        : "+f"(d[0]), "+f"(d[1]), "+f"(d[2]), "+f"(d[3])
        : "r"(a[0]), "r"(a[1]), "r"(a[2]), "r"(a[3]), "r"(b0), "r"(b1));
}

__global__ void prep_kernel(const void* __restrict__ ptr_raw,
                            int num_dags, int num_nodes) {
    const int*       p32 = (const int*)ptr_raw;
    const long long* p64 = (const long long*)ptr_raw;
    const bool is32 = (p32[num_dags] == num_nodes);
    const int w = (blockIdx.x * blockDim.x + threadIdx.x) >> 5;
    const int lane = threadIdx.x & 31;
    if (w > num_dags) return;
    if (w == num_dags) { if (lane == 0) g_ptr[num_dags] = num_nodes; return; }
    const int b0 = is32 ? p32[w] : (int)p64[w];
    const int b1 = is32 ? p32[w + 1] : (int)p64[w + 1];
    if (lane == 0) g_ptr[w] = b0;
    if (lane < 16)
        ((float4*)&g_acc[(size_t)w * 64])[lane] = make_float4(0.f, 0.f, 0.f, 0.f);
    for (int i = b0 + lane; i < b1; i += 32) g_seg[i] = w;
}

// smem: W1[48][72]f16 @0 (6912), W2[64][72] @6912 (9216),
//       b1 @16128, b2 @16384; per-warp act scratch 3584B @16640 + w*3584
#define OFF_W1  0
#define OFF_W2  6912
#define OFF_B1  16128
#define OFF_B2  16384
#define OFF_SCR 16640
#define SCR_WARP 3584
#define SMEM_SZ (OFF_SCR + 4 * SCR_WARP)

__global__ __launch_bounds__(128, 4) void mma_seg_kernel(
    const float* __restrict__ h_node, const float* __restrict__ x,
    const float* __restrict__ W1, const float* __restrict__ b1,
    const float* __restrict__ W2, const float* __restrict__ b2,
    int num_nodes, int ntiles)
{
    extern __shared__ __align__(16) unsigned char sm[];
    const int tid = threadIdx.x, lane = tid & 31, w = tid >> 5;

    for (int i = tid; i < 48 * 72; i += 128) {
        int k = i / 72, n = i % 72;
        float v = (k < 37 && n < 64) ? W1[k * 64 + n] : 0.0f;
        *(__half*)(sm + OFF_W1 + i * 2) = __float2half_rn(v);
    }
    for (int i = tid; i < 64 * 72; i += 128) {
        int k = i / 72, n = i % 72;
        float v = (n < 64) ? W2[k * 64 + n] : 0.0f;
        *(__half*)(sm + OFF_W2 + i * 2) = __float2half_rn(v);
    }
    if (tid < 64) {
        ((float*)(sm + OFF_B1))[tid] = b1[tid];
        ((float*)(sm + OFF_B2))[tid] = b2[tid];
    }
    __syncthreads();

    unsigned char* scrp = sm + OFF_SCR + w * SCR_WARP;
    const u32 scr = smem_u32(scrp);
    const u32 w1s = smem_u32(sm + OFF_W1);
    const u32 w2s = smem_u32(sm + OFF_W2);
    const float* B1s = (const float*)(sm + OFF_B1);
    const float* B2s = (const float*)(sm + OFF_B2);

    const int g = lane >> 2, t = lane & 3;
    const int lrow = lane & 15, lcs = lane >> 4;
    const unsigned FULL = 0xffffffffu;
    const int wid_g = blockIdx.x * 4 + w, nW = gridDim.x * 4;

    for (int tile = wid_g; tile < ntiles; tile += nW) {
        const int node0 = tile * 32;
        const int node = node0 + lane;
        const bool valid = node < num_nodes;
        const int node_c = valid ? node : (num_nodes - 1);   // clamped, branchless

        // ---- load (always, clamped) + convert to packed fp16 ----
        u32 ah[24];
        {
            const float* xp = x + (size_t)node_c * 5;
            float x0 = xp[0], x1 = xp[1], x2 = xp[2], x3 = xp[3], x4 = xp[4];
            const float4* hp = (const float4*)(h_node + (size_t)node_c * 32);
            ah[0] = f16pair(x0, x1);
            ah[1] = f16pair(x2, x3);
            float carry = x4;
#pragma unroll
            for (int i = 0; i < 8; i++) {
                float4 v4 = hp[i];
                ah[2 + 2 * i] = f16pair(carry, v4.x);
                ah[3 + 2 * i] = f16pair(v4.y, v4.z);
                carry = v4.w;
            }
            ah[18] = f16pair(carry, 0.0f);
            ah[19] = 0u; ah[20] = 0u; ah[21] = 0u; ah[22] = 0u; ah[23] = 0u;
        }
        const int seg = valid ? g_seg[node] : -1;

        // segment classification
        int segup = __shfl_up_sync(FULL, seg, 1);
        bool head = valid && (lane == 0 || segup != seg);
        unsigned bm = __ballot_sync(FULL, head);
        const int nsegs = __popc(bm);              // >= 1 always (lane 0 valid)
        const int segA = __shfl_sync(FULL, seg, __ffs(bm) - 1);
        int segB = 0, rowb = 32;
        if (nsegs >= 2) {
            unsigned bm2 = bm & (bm - 1);
            rowb = __ffs(bm2) - 1;
            segB = __shfl_sync(FULL, seg, rowb);
        }

        __syncwarp();  // scratch reuse vs previous iteration
        {
            uint4* dh = (uint4*)(scrp + lane * 112);
#pragma unroll
            for (int j = 0; j < 6; j++)
                dh[j] = make_uint4(ah[4*j], ah[4*j+1], ah[4*j+2], ah[4*j+3]);
        }
        __syncwarp();

        // layer-1 A fragments (M32 K48)
        u32 a1[2][3][4];
#pragma unroll
        for (int mt = 0; mt < 2; mt++)
#pragma unroll
            for (int kt = 0; kt < 3; kt++)
                ldsm_x4(scr + (mt * 16 + lrow) * 112 + (kt * 16 + lcs * 8) * 2,
                        a1[mt][kt]);

        // ---- layer 1 MMA -> layer-2 A frags in registers ----
        u32 a2[2][4][4];
#pragma unroll
        for (int half = 0; half < 2; half++) {
            float d[2][4][4];
#pragma unroll
            for (int ntl = 0; ntl < 4; ntl++) {
                float2 bb = *(const float2*)(B1s + (half * 4 + ntl) * 8 + 2 * t);
#pragma unroll
                for (int mt = 0; mt < 2; mt++) {
                    d[mt][ntl][0] = bb.x; d[mt][ntl][1] = bb.y;
                    d[mt][ntl][2] = bb.x; d[mt][ntl][3] = bb.y;
                }
            }
#pragma unroll
            for (int np = 0; np < 2; np++) {
                int npg = half * 2 + np;
                u32 bh[3][4];
#pragma unroll
                for (int kt = 0; kt < 3; kt++)
                    ldsm_x4t(w1s + (kt * 16 + lrow) * 144 + (npg * 16 + lcs * 8) * 2,
                             bh[kt]);
#pragma unroll
                for (int mt = 0; mt < 2; mt++)
#pragma unroll
                    for (int kt = 0; kt < 3; kt++)
#pragma unroll
                        for (int hh = 0; hh < 2; hh++)
                            mma_f16(d[mt][np * 2 + hh], a1[mt][kt],
                                    bh[kt][2*hh], bh[kt][2*hh+1]);
            }
#pragma unroll
            for (int mt = 0; mt < 2; mt++)
#pragma unroll
                for (int ntl = 0; ntl < 4; ntl++) {
                    int ng = half * 4 + ntl;
                    int ktg = ng >> 1, sub = ng & 1;
                    a2[mt][ktg][sub * 2 + 0] =
                        f16pair(fmaxf(d[mt][ntl][0], 0.f), fmaxf(d[mt][ntl][1], 0.f));
                    a2[mt][ktg][sub * 2 + 1] =
                        f16pair(fmaxf(d[mt][ntl][2], 0.f), fmaxf(d[mt][ntl][3], 0.f));
                }
        }

        // ---- layer 2 MMA; epilogue reduce ----
#pragma unroll
        for (int half = 0; half < 2; half++) {
            float d[2][4][4];
#pragma unroll
            for (int ntl = 0; ntl < 4; ntl++) {
                float2 bb = *(const float2*)(B2s + (half * 4 + ntl) * 8 + 2 * t);
#pragma unroll
                for (int mt = 0; mt < 2; mt++) {
                    d[mt][ntl][0] = bb.x; d[mt][ntl][1] = bb.y;
                    d[mt][ntl][2] = bb.x; d[mt][ntl][3] = bb.y;
                }
            }
#pragma unroll
            for (int np = 0; np < 2; np++) {
                int npg = half * 2 + np;
                u32 bh[4][4];
#pragma unroll
                for (int kt = 0; kt < 4; kt++)
                    ldsm_x4t(w2s + (kt * 16 + lrow) * 144 + (npg * 16 + lcs * 8) * 2,
                             bh[kt]);
#pragma unroll
                for (int mt = 0; mt < 2; mt++)
#pragma unroll
                    for (int kt = 0; kt < 4; kt++)
#pragma unroll
                        for (int hh = 0; hh < 2; hh++)
                            mma_f16(d[mt][np * 2 + hh], a2[mt][kt],
                                    bh[kt][2*hh], bh[kt][2*hh+1]);
            }

            // relu + validity
#pragma unroll
            for (int mt = 0; mt < 2; mt++)
#pragma unroll
                for (int ntl = 0; ntl < 4; ntl++) {
                    bool ok0 = (node0 + mt * 16 + g) < num_nodes;
                    bool ok1 = (node0 + mt * 16 + g + 8) < num_nodes;
                    d[mt][ntl][0] = ok0 ? fmaxf(d[mt][ntl][0], 0.f) : 0.f;
                    d[mt][ntl][1] = ok0 ? fmaxf(d[mt][ntl][1], 0.f) : 0.f;
                    d[mt][ntl][2] = ok1 ? fmaxf(d[mt][ntl][2], 0.f) : 0.f;
                    d[mt][ntl][3] = ok1 ? fmaxf(d[mt][ntl][3], 0.f) : 0.f;
                }

            if (nsegs == 1) {       // 73% of tiles: single-bucket colsum
#pragma unroll
                for (int ntl = 0; ntl < 4; ntl++) {
                    float s0 = d[0][ntl][0] + d[0][ntl][2] + d[1][ntl][0] + d[1][ntl][2];
                    float s1 = d[0][ntl][1] + d[0][ntl][3] + d[1][ntl][1] + d[1][ntl][3];
#pragma unroll
                    for (int m = 4; m <= 16; m <<= 1) {
                        s0 += __shfl_xor_sync(FULL, s0, m);
                        s1 += __shfl_xor_sync(FULL, s1, m);
                    }
                    if (g == 0) {
                        int c = half * 32 + ntl * 8 + 2 * t;
                        atomicAdd(&g_acc[(size_t)segA * 64 + c], s0);
                        atomicAdd(&g_acc[(size_t)segA * 64 + c + 1], s1);
                    }
                }
            } else if (nsegs == 2) {  // two-bucket colsum
#pragma unroll
                for (int ntl = 0; ntl < 4; ntl++) {
                    float sA0 = 0.f, sA1 = 0.f, sB0 = 0.f, sB1v = 0.f;
#pragma unroll
                    for (int mt = 0; mt < 2; mt++) {
                        int r0 = mt * 16 + g, r1 = r0 + 8;
                        if (r0 < rowb) { sA0 += d[mt][ntl][0]; sA1 += d[mt][ntl][1]; }
                        else           { sB0 += d[mt][ntl][0]; sB1v += d[mt][ntl][1]; }
                        if (r1 < rowb) { sA0 += d[mt][ntl][2]; sA1 += d[mt][ntl][3]; }
                        else           { sB0 += d[mt][ntl][2]; sB1v += d[mt][ntl][3]; }
                    }
#pragma unroll
                    for (int m = 4; m <= 16; m <<= 1) {
                        sA0 += __shfl_xor_sync(FULL, sA0, m);
                        sA1 += __shfl_xor_sync(FULL, sA1, m);
                        sB0 += __shfl_xor_sync(FULL, sB0, m);
                        sB1v += __shfl_xor_sync(FULL, sB1v, m);
                    }
                    if (g == 0) {
                        int c = half * 32 + ntl * 8 + 2 * t;
                        atomicAdd(&g_acc[(size_t)segA * 64 + c], sA0);
                        atomicAdd(&g_acc[(size_t)segA * 64 + c + 1], sA1);
                        atomicAdd(&g_acc[(size_t)segB * 64 + c], sB0);
                        atomicAdd(&g_acc[(size_t)segB * 64 + c + 1], sB1v);
                    }
                }
            } else {  // rare (>=3 segs): direct guarded atomics
#pragma unroll
                for (int mt = 0; mt < 2; mt++) {
                    int s0 = __shfl_sync(FULL, seg, mt * 16 + g);
                    int s1 = __shfl_sync(FULL, seg, mt * 16 + g + 8);
#pragma unroll
                    for (int ntl = 0; ntl < 4; ntl++) {
                        int c = (half * 4 + ntl) * 8 + 2 * t;
                        if (s0 >= 0) {
                            atomicAdd(&g_acc[(size_t)s0 * 64 + c], d[mt][ntl][0]);
                            atomicAdd(&g_acc[(size_t)s0 * 64 + c + 1], d[mt][ntl][1]);
                        }
                        if (s1 >= 0) {
                            atomicAdd(&g_acc[(size_t)s1 * 64 + c], d[mt][ntl][2]);
                            atomicAdd(&g_acc[(size_t)s1 * 64 + c + 1], d[mt][ntl][3]);
                        }
                    }
                }
            }
        }
    }
}

__global__ __launch_bounds__(256) void final_kernel(
    const float* __restrict__ W3, const float* __restrict__ b3,
    float* __restrict__ out, int num_dags)
{
    __shared__ __align__(16) float sW3[64 * 32];
    __shared__ float sB3[32];
    const int tid = threadIdx.x;
    for (int i = tid; i < 64 * 32; i += 256) sW3[i] = W3[i];
    if (tid < 32) sB3[tid] = b3[tid];
    __syncthreads();
    const int d = blockIdx.x * 8 + (tid >> 5);
    const int e = tid & 31;
    if (d >= num_dags) return;
    const float cnt = (float)(g_ptr[d + 1] - g_ptr[d]);
    float acc = cnt * sB3[e];
    const float* gd = &g_acc[(size_t)d * 64];
#pragma unroll
    for (int k = 0; k < 64; k++)
        acc = fmaf(gd[k], sW3[k * 32 + e], acc);
    out[(size_t)d * 32 + e] = acc;
}

extern "C" void kernel_launch(void* const* d_in, const int* in_sizes, int n_in,
                              void* d_out, int out_size)
{
    const float* h_node = (const float*)d_in[0];
    const float* x      = (const float*)d_in[1];
    const float* W1     = (const float*)d_in[2];
    const float* b1     = (const float*)d_in[3];
    const float* W2     = (const float*)d_in[4];
    const float* b2     = (const float*)d_in[5];
    const float* W3     = (const float*)d_in[6];
    const float* b3     = (const float*)d_in[7];
    const void*  ptr    = (const void*)d_in[8];

    const int num_nodes = in_sizes[0] / 32;
    const int num_dags  = in_sizes[8] - 1;
    const int ntiles    = (num_nodes + 31) / 32;

    static int grid_cached = 0;
    if (!grid_cached) {
        cudaFuncSetAttribute(mma_seg_kernel,
                             cudaFuncAttributeMaxDynamicSharedMemorySize, SMEM_SZ);
        int occ = 0, sms = 0;
        cudaOccupancyMaxActiveBlocksPerMultiprocessor(&occ, mma_seg_kernel,
                                                      128, SMEM_SZ);
        cudaDeviceGetAttribute(&sms, cudaDevAttrMultiProcessorCount, 0);
        if (occ < 1) occ = 1;
        if (sms < 1) sms = 148;
        grid_cached = occ * sms;
    }

    prep_kernel<<<((num_dags + 1) * 32 + 255) / 256, 256>>>(ptr, num_dags, num_nodes);

    int grid = grid_cached;
    if (grid > (ntiles + 3) / 4) grid = (ntiles + 3) / 4;
    mma_seg_kernel<<<grid, 128, SMEM_SZ>>>(h_node, x, W1, b1, W2, b2,
                                           num_nodes, ntiles);

    final_kernel<<<(num_dags + 7) / 8, 256>>>(W3, b3, (float*)d_out, num_dags);
}

// round 17
// speedup vs baseline: 1.0557x; 1.0071x over previous
#include <cuda_runtime.h>
#include <cuda_fp16.h>

// DagEncoder via warp-level fp16 mma.sync (single-term fp16 weights).
// R17 = R16 + uint16 seg map (halves prep traffic) + edge-tile branch for
// validity masking + f16x2 relu in layer-1 epilogue.

#define MAX_DAGS  20000
#define MAX_NODES 2000000
__device__ float          g_acc[MAX_DAGS * 64];
__device__ int            g_ptr[MAX_DAGS + 1];
__device__ unsigned short g_seg[MAX_NODES];

typedef unsigned int u32;

__device__ __forceinline__ u32 smem_u32(const void* p) {
    u32 a;
    asm("{ .reg .u64 t; cvta.to.shared.u64 t, %1; cvt.u32.u64 %0, t; }"
        : "=r"(a) : "l"(p));
    return a;
}
__device__ __forceinline__ u32 f16pair(float v0, float v1) {
    u32 d;
    asm("cvt.rn.f16x2.f32 %0, %1, %2;" : "=r"(d) : "f"(v1), "f"(v0));
    return d;
}
__device__ __forceinline__ u32 relu2(u32 v) {
    u32 r;
    asm("max.f16x2 %0, %1, %2;" : "=r"(r) : "r"(v), "r"(0u));
    return r;
}
__device__ __forceinline__ void ldsm_x4(u32 a, u32* r) {
    asm volatile("ldmatrix.sync.aligned.m8n8.x4.shared.b16 {%0,%1,%2,%3}, [%4];"
        : "=r"(r[0]), "=r"(r[1]), "=r"(r[2]), "=r"(r[3]) : "r"(a));
}
__device__ __forceinline__ void ldsm_x4t(u32 a, u32* r) {
    asm volatile("ldmatrix.sync.aligned.m8n8.x4.trans.shared.b16 {%0,%1,%2,%3}, [%4];"
        : "=r"(r[0]), "=r"(r[1]), "=r"(r[2]), "=r"(r[3]) : "r"(a));
}
__device__ __forceinline__ void mma_f16(float* d, const u32* a, u32 b0, u32 b1) {
    asm("mma.sync.aligned.m16n8k16.row.col.f32.f16.f16.f32 "
        "{%0,%1,%2,%3},{%4,%5,%6,%7},{%8,%9},{%0,%1,%2,%3};"
        : "+f"(d[0]), "+f"(d[1]), "+f"(d[2]), "+f"(d[3])
        : "r"(a[0]), "r"(a[1]), "r"(a[2]), "r"(a[3]), "r"(b0), "r"(b1));
}

__global__ void prep_kernel(const void* __restrict__ ptr_raw,
                            int num_dags, int num_nodes) {
    const int*       p32 = (const int*)ptr_raw;
    const long long* p64 = (const long long*)ptr_raw;
    const bool is32 = (p32[num_dags] == num_nodes);
    const int w = (blockIdx.x * blockDim.x + threadIdx.x) >> 5;
    const int lane = threadIdx.x & 31;
    if (w > num_dags) return;
    if (w == num_dags) { if (lane == 0) g_ptr[num_dags] = num_nodes; return; }
    const int b0 = is32 ? p32[w] : (int)p64[w];
    const int b1 = is32 ? p32[w + 1] : (int)p64[w + 1];
    if (lane == 0) g_ptr[w] = b0;
    if (lane < 16)
        ((float4*)&g_acc[(size_t)w * 64])[lane] = make_float4(0.f, 0.f, 0.f, 0.f);
    const unsigned short ws = (unsigned short)w;
    for (int i = b0 + lane; i < b1; i += 32) g_seg[i] = ws;
}

// smem: W1[48][72]f16 @0 (6912), W2[64][72] @6912 (9216),
//       b1 @16128, b2 @16384; per-warp act scratch 3584B @16640 + w*3584
#define OFF_W1  0
#define OFF_W2  6912
#define OFF_B1  16128
#define OFF_B2  16384
#define OFF_SCR 16640
#define SCR_WARP 3584
#define SMEM_SZ (OFF_SCR + 4 * SCR_WARP)

__global__ __launch_bounds__(128, 4) void mma_seg_kernel(
    const float* __restrict__ h_node, const float* __restrict__ x,
    const float* __restrict__ W1, const float* __restrict__ b1,
    const float* __restrict__ W2, const float* __restrict__ b2,
    int num_nodes, int ntiles)
{
    extern __shared__ __align__(16) unsigned char sm[];
    const int tid = threadIdx.x, lane = tid & 31, w = tid >> 5;

    for (int i = tid; i < 48 * 72; i += 128) {
        int k = i / 72, n = i % 72;
        float v = (k < 37 && n < 64) ? W1[k * 64 + n] : 0.0f;
        *(__half*)(sm + OFF_W1 + i * 2) = __float2half_rn(v);
    }
    for (int i = tid; i < 64 * 72; i += 128) {
        int k = i / 72, n = i % 72;
        float v = (n < 64) ? W2[k * 64 + n] : 0.0f;
        *(__half*)(sm + OFF_W2 + i * 2) = __float2half_rn(v);
    }
    if (tid < 64) {
        ((float*)(sm + OFF_B1))[tid] = b1[tid];
        ((float*)(sm + OFF_B2))[tid] = b2[tid];
    }
    __syncthreads();

    unsigned char* scrp = sm + OFF_SCR + w * SCR_WARP;
    const u32 scr = smem_u32(scrp);
    const u32 w1s = smem_u32(sm + OFF_W1);
    const u32 w2s = smem_u32(sm + OFF_W2);
    const float* B1s = (const float*)(sm + OFF_B1);
    const float* B2s = (const float*)(sm + OFF_B2);

    const int g = lane >> 2, t = lane & 3;
    const int lrow = lane & 15, lcs = lane >> 4;
    const unsigned FULL = 0xffffffffu;
    const int wid_g = blockIdx.x * 4 + w, nW = gridDim.x * 4;

    for (int tile = wid_g; tile < ntiles; tile += nW) {
        const int node0 = tile * 32;
        const int node = node0 + lane;
        const bool edge = (node0 + 32) > num_nodes;    // warp-uniform
        const bool valid = node < num_nodes;
        const int node_c = valid ? node : (num_nodes - 1);

        // ---- load (always, clamped) + convert to packed fp16 ----
        u32 ah[24];
        {
            const float* xp = x + (size_t)node_c * 5;
            float x0 = xp[0], x1 = xp[1], x2 = xp[2], x3 = xp[3], x4 = xp[4];
            const float4* hp = (const float4*)(h_node + (size_t)node_c * 32);
            ah[0] = f16pair(x0, x1);
            ah[1] = f16pair(x2, x3);
            float carry = x4;
#pragma unroll
            for (int i = 0; i < 8; i++) {
                float4 v4 = hp[i];
                ah[2 + 2 * i] = f16pair(carry, v4.x);
                ah[3 + 2 * i] = f16pair(v4.y, v4.z);
                carry = v4.w;
            }
            ah[18] = f16pair(carry, 0.0f);
            ah[19] = 0u; ah[20] = 0u; ah[21] = 0u; ah[22] = 0u; ah[23] = 0u;
        }
        const int seg = valid ? (int)g_seg[node] : -1;

        // segment classification
        int segup = __shfl_up_sync(FULL, seg, 1);
        bool head = valid && (lane == 0 || segup != seg);
        unsigned bm = __ballot_sync(FULL, head);
        const int nsegs = __popc(bm);              // >= 1 always (lane 0 valid)
        const int segA = __shfl_sync(FULL, seg, __ffs(bm) - 1);
        int segB = 0, rowb = 32;
        if (nsegs >= 2) {
            unsigned bm2 = bm & (bm - 1);
            rowb = __ffs(bm2) - 1;
            segB = __shfl_sync(FULL, seg, rowb);
        }

        __syncwarp();  // scratch reuse vs previous iteration
        {
            uint4* dh = (uint4*)(scrp + lane * 112);
#pragma unroll
            for (int j = 0; j < 6; j++)
                dh[j] = make_uint4(ah[4*j], ah[4*j+1], ah[4*j+2], ah[4*j+3]);
        }
        __syncwarp();

        // layer-1 A fragments (M32 K48)
        u32 a1[2][3][4];
#pragma unroll
        for (int mt = 0; mt < 2; mt++)
#pragma unroll
            for (int kt = 0; kt < 3; kt++)
                ldsm_x4(scr + (mt * 16 + lrow) * 112 + (kt * 16 + lcs * 8) * 2,
                        a1[mt][kt]);

        // ---- layer 1 MMA -> layer-2 A frags in registers ----
        u32 a2[2][4][4];
#pragma unroll
        for (int half = 0; half < 2; half++) {
            float d[2][4][4];
#pragma unroll
            for (int ntl = 0; ntl < 4; ntl++) {
                float2 bb = *(const float2*)(B1s + (half * 4 + ntl) * 8 + 2 * t);
#pragma unroll
                for (int mt = 0; mt < 2; mt++) {
                    d[mt][ntl][0] = bb.x; d[mt][ntl][1] = bb.y;
                    d[mt][ntl][2] = bb.x; d[mt][ntl][3] = bb.y;
                }
            }
#pragma unroll
            for (int np = 0; np < 2; np++) {
                int npg = half * 2 + np;
                u32 bh[3][4];
#pragma unroll
                for (int kt = 0; kt < 3; kt++)
                    ldsm_x4t(w1s + (kt * 16 + lrow) * 144 + (npg * 16 + lcs * 8) * 2,
                             bh[kt]);
#pragma unroll
                for (int mt = 0; mt < 2; mt++)
#pragma unroll
                    for (int kt = 0; kt < 3; kt++)
#pragma unroll
                        for (int hh = 0; hh < 2; hh++)
                            mma_f16(d[mt][np * 2 + hh], a1[mt][kt],
                                    bh[kt][2*hh], bh[kt][2*hh+1]);
            }
            // pack then relu in f16x2 (saves 16 fmax slots)
#pragma unroll
            for (int mt = 0; mt < 2; mt++)
#pragma unroll
                for (int ntl = 0; ntl < 4; ntl++) {
                    int ng = half * 4 + ntl;
                    int ktg = ng >> 1, sub = ng & 1;
                    a2[mt][ktg][sub * 2 + 0] = relu2(f16pair(d[mt][ntl][0], d[mt][ntl][1]));
                    a2[mt][ktg][sub * 2 + 1] = relu2(f16pair(d[mt][ntl][2], d[mt][ntl][3]));
                }
        }

        // ---- layer 2 MMA; epilogue reduce ----
#pragma unroll
        for (int half = 0; half < 2; half++) {
            float d[2][4][4];
#pragma unroll
            for (int ntl = 0; ntl < 4; ntl++) {
                float2 bb = *(const float2*)(B2s + (half * 4 + ntl) * 8 + 2 * t);
#pragma unroll
                for (int mt = 0; mt < 2; mt++) {
                    d[mt][ntl][0] = bb.x; d[mt][ntl][1] = bb.y;
                    d[mt][ntl][2] = bb.x; d[mt][ntl][3] = bb.y;
                }
            }
#pragma unroll
            for (int np = 0; np < 2; np++) {
                int npg = half * 2 + np;
                u32 bh[4][4];
#pragma unroll
                for (int kt = 0; kt < 4; kt++)
                    ldsm_x4t(w2s + (kt * 16 + lrow) * 144 + (npg * 16 + lcs * 8) * 2,
                             bh[kt]);
#pragma unroll
                for (int mt = 0; mt < 2; mt++)
#pragma unroll
                    for (int kt = 0; kt < 4; kt++)
#pragma unroll
                        for (int hh = 0; hh < 2; hh++)
                            mma_f16(d[mt][np * 2 + hh], a2[mt][kt],
                                    bh[kt][2*hh], bh[kt][2*hh+1]);
            }

            // relu (always) + validity masking only on the single edge tile
#pragma unroll
            for (int mt = 0; mt < 2; mt++)
#pragma unroll
                for (int ntl = 0; ntl < 4; ntl++) {
                    d[mt][ntl][0] = fmaxf(d[mt][ntl][0], 0.f);
                    d[mt][ntl][1] = fmaxf(d[mt][ntl][1], 0.f);
                    d[mt][ntl][2] = fmaxf(d[mt][ntl][2], 0.f);
                    d[mt][ntl][3] = fmaxf(d[mt][ntl][3], 0.f);
                }
            if (edge) {
#pragma unroll
                for (int mt = 0; mt < 2; mt++) {
                    bool ok0 = (node0 + mt * 16 + g) < num_nodes;
                    bool ok1 = (node0 + mt * 16 + g + 8) < num_nodes;
#pragma unroll
                    for (int ntl = 0; ntl < 4; ntl++) {
                        if (!ok0) { d[mt][ntl][0] = 0.f; d[mt][ntl][1] = 0.f; }
                        if (!ok1) { d[mt][ntl][2] = 0.f; d[mt][ntl][3] = 0.f; }
                    }
                }
            }

            if (nsegs == 1) {       // 73% of tiles: single-bucket colsum
#pragma unroll
                for (int ntl = 0; ntl < 4; ntl++) {
                    float s0 = d[0][ntl][0] + d[0][ntl][2] + d[1][ntl][0] + d[1][ntl][2];
                    float s1 = d[0][ntl][1] + d[0][ntl][3] + d[1][ntl][1] + d[1][ntl][3];
#pragma unroll
                    for (int m = 4; m <= 16; m <<= 1) {
                        s0 += __shfl_xor_sync(FULL, s0, m);
                        s1 += __shfl_xor_sync(FULL, s1, m);
                    }
                    if (g == 0) {
                        int c = half * 32 + ntl * 8 + 2 * t;
                        atomicAdd(&g_acc[(size_t)segA * 64 + c], s0);
                        atomicAdd(&g_acc[(size_t)segA * 64 + c + 1], s1);
                    }
                }
            } else if (nsegs == 2) {  // two-bucket colsum
#pragma unroll
                for (int ntl = 0; ntl < 4; ntl++) {
                    float sA0 = 0.f, sA1 = 0.f, sB0 = 0.f, sB1v = 0.f;
#pragma unroll
                    for (int mt = 0; mt < 2; mt++) {
                        int r0 = mt * 16 + g, r1 = r0 + 8;
                        if (r0 < rowb) { sA0 += d[mt][ntl][0]; sA1 += d[mt][ntl][1]; }
                        else           { sB0 += d[mt][ntl][0]; sB1v += d[mt][ntl][1]; }
                        if (r1 < rowb) { sA0 += d[mt][ntl][2]; sA1 += d[mt][ntl][3]; }
                        else           { sB0 += d[mt][ntl][2]; sB1v += d[mt][ntl][3]; }
                    }
#pragma unroll
                    for (int m = 4; m <= 16; m <<= 1) {
                        sA0 += __shfl_xor_sync(FULL, sA0, m);
                        sA1 += __shfl_xor_sync(FULL, sA1, m);
                        sB0 += __shfl_xor_sync(FULL, sB0, m);
                        sB1v += __shfl_xor_sync(FULL, sB1v, m);
                    }
                    if (g == 0) {
                        int c = half * 32 + ntl * 8 + 2 * t;
                        atomicAdd(&g_acc[(size_t)segA * 64 + c], sA0);
                        atomicAdd(&g_acc[(size_t)segA * 64 + c + 1], sA1);
                        atomicAdd(&g_acc[(size_t)segB * 64 + c], sB0);
                        atomicAdd(&g_acc[(size_t)segB * 64 + c + 1], sB1v);
                    }
                }
            } else {  // rare (>=3 segs): direct guarded atomics
#pragma unroll
                for (int mt = 0; mt < 2; mt++) {
                    int s0 = __shfl_sync(FULL, seg, mt * 16 + g);
                    int s1 = __shfl_sync(FULL, seg, mt * 16 + g + 8);
#pragma unroll
                    for (int ntl = 0; ntl < 4; ntl++) {
                        int c = (half * 4 + ntl) * 8 + 2 * t;
                        if (s0 >= 0) {
                            atomicAdd(&g_acc[(size_t)s0 * 64 + c], d[mt][ntl][0]);
                            atomicAdd(&g_acc[(size_t)s0 * 64 + c + 1], d[mt][ntl][1]);
                        }
                        if (s1 >= 0) {
                            atomicAdd(&g_acc[(size_t)s1 * 64 + c], d[mt][ntl][2]);
                            atomicAdd(&g_acc[(size_t)s1 * 64 + c + 1], d[mt][ntl][3]);
                        }
                    }
                }
            }
        }
    }
}

__global__ __launch_bounds__(256) void final_kernel(
    const float* __restrict__ W3, const float* __restrict__ b3,
    float* __restrict__ out, int num_dags)
{
    __shared__ __align__(16) float sW3[64 * 32];
    __shared__ float sB3[32];
    const int tid = threadIdx.x;
    for (int i = tid; i < 64 * 32; i += 256) sW3[i] = W3[i];
    if (tid < 32) sB3[tid] = b3[tid];
    __syncthreads();
    const int d = blockIdx.x * 8 + (tid >> 5);
    const int e = tid & 31;
    if (d >= num_dags) return;
    const float cnt = (float)(g_ptr[d + 1] - g_ptr[d]);
    float acc = cnt * sB3[e];
    const float* gd = &g_acc[(size_t)d * 64];
#pragma unroll
    for (int k = 0; k < 64; k++)
        acc = fmaf(gd[k], sW3[k * 32 + e], acc);
    out[(size_t)d * 32 + e] = acc;
}

extern "C" void kernel_launch(void* const* d_in, const int* in_sizes, int n_in,
                              void* d_out, int out_size)
{
    const float* h_node = (const float*)d_in[0];
    const float* x      = (const float*)d_in[1];
    const float* W1     = (const float*)d_in[2];
    const float* b1     = (const float*)d_in[3];
    const float* W2     = (const float*)d_in[4];
    const float* b2     = (const float*)d_in[5];
    const float* W3     = (const float*)d_in[6];
    const float* b3     = (const float*)d_in[7];
    const void*  ptr    = (const void*)d_in[8];

    const int num_nodes = in_sizes[0] / 32;
    const int num_dags  = in_sizes[8] - 1;
    const int ntiles    = (num_nodes + 31) / 32;

    static int grid_cached = 0;
    if (!grid_cached) {
        cudaFuncSetAttribute(mma_seg_kernel,
                             cudaFuncAttributeMaxDynamicSharedMemorySize, SMEM_SZ);
        int occ = 0, sms = 0;
        cudaOccupancyMaxActiveBlocksPerMultiprocessor(&occ, mma_seg_kernel,
                                                      128, SMEM_SZ);
        cudaDeviceGetAttribute(&sms, cudaDevAttrMultiProcessorCount, 0);
        if (occ < 1) occ = 1;
        if (sms < 1) sms = 148;
        grid_cached = occ * sms;
    }

    prep_kernel<<<((num_dags + 1) * 32 + 255) / 256, 256>>>(ptr, num_dags, num_nodes);

    int grid = grid_cached;
    if (grid > (ntiles + 3) / 4) grid = (ntiles + 3) / 4;
    mma_seg_kernel<<<grid, 128, SMEM_SZ>>>(h_node, x, W1, b1, W2, b2,
                                           num_nodes, ntiles);

    final_kernel<<<(num_dags + 7) / 8, 256>>>(W3, b3, (float*)d_out, num_dags);
}